// round 1
// baseline (speedup 1.0000x reference)
#include <cuda_runtime.h>
#include <math.h>

#define T_TOKENS 4096
#define HID 2560
#define NEXP 16
#define TOPK 6
#define TI 1536
#define VI 512
#define SI 3072
#define NPAIRS (T_TOKENS*TOPK)   /* 24576 */
#define NSLOTS 32

// ---------------- scratch (device globals; no runtime allocation) ----------
__device__ float g_hexp[(size_t)NPAIRS * TI];    // silu(g)*u per (token,expert) pair
__device__ float g_oexp[(size_t)NPAIRS * HID];   // weighted down-proj per pair
__device__ float g_hsh[(size_t)T_TOKENS * SI];   // shared expert hidden
__device__ float g_osh[(size_t)T_TOKENS * HID];  // shared expert output
__device__ int   g_slot_tok[NPAIRS];
__device__ float g_slot_w[NPAIRS];
__device__ int   g_pair_row[NPAIRS];
__device__ int   g_cnt[NSLOTS];
__device__ int   g_off[NSLOTS];
__device__ int   g_cur[NSLOTS];
__device__ int   g_tope[NPAIRS];
__device__ float g_topw[NPAIRS];

// ---------------- small kernels -------------------------------------------
__global__ void init_kernel() {
    if (threadIdx.x < NSLOTS) { g_cnt[threadIdx.x] = 0; g_cur[threadIdx.x] = 0; }
}

// One block per token: fp32 router, softmax, bias-corrected top-6, normalized weights.
__global__ void __launch_bounds__(128)
router_kernel(const float* __restrict__ x, const int* __restrict__ tt,
              const float* __restrict__ tw, const float* __restrict__ tb,
              const float* __restrict__ vw, const float* __restrict__ vb,
              float* __restrict__ out_logits)
{
    int t = blockIdx.x;
    int tid = threadIdx.x;
    bool vis = (tt[t] != 0);
    const float* w = vis ? vw : tw;
    const float* b = vis ? vb : tb;

    __shared__ float xs[HID];
    __shared__ float lg[NEXP];
    const float* xr = x + (size_t)t * HID;
    for (int i = tid; i < HID; i += 128) xs[i] = xr[i];
    __syncthreads();

    int e = tid >> 3;          // 16 groups of 8 threads, one expert each
    int l = tid & 7;
    const float* we = w + (size_t)e * HID;
    float s = 0.f;
    for (int k = l; k < HID; k += 8) s += xs[k] * we[k];
    for (int o = 4; o; o >>= 1) s += __shfl_down_sync(0xffffffffu, s, o);
    if (l == 0) lg[e] = s;
    __syncthreads();

    if (tid < NEXP) out_logits[(size_t)t * NEXP + tid] = lg[tid];

    if (tid == 0) {
        float mx = lg[0];
        for (int i = 1; i < NEXP; i++) mx = fmaxf(mx, lg[i]);
        float p[NEXP]; float sum = 0.f;
        for (int i = 0; i < NEXP; i++) { p[i] = expf(lg[i] - mx); sum += p[i]; }
        float inv = 1.f / sum;
        float corr[NEXP];
        for (int i = 0; i < NEXP; i++) { p[i] *= inv; corr[i] = p[i] + b[i]; }

        bool used[NEXP];
        for (int i = 0; i < NEXP; i++) used[i] = false;
        int   idxs[TOPK]; float ws[TOPK]; float wsum = 0.f;
        for (int j = 0; j < TOPK; j++) {
            int bi = -1; float bv = -1e30f;
            for (int i = 0; i < NEXP; i++)
                if (!used[i] && corr[i] > bv) { bv = corr[i]; bi = i; }
            used[bi] = true; idxs[j] = bi; ws[j] = p[bi]; wsum += p[bi];
        }
        float invw = 1.f / fmaxf(wsum, 1e-12f);
        int mbase = vis ? 16 : 0;
        for (int j = 0; j < TOPK; j++) {
            g_tope[t*TOPK + j] = mbase + idxs[j];
            g_topw[t*TOPK + j] = ws[j] * invw;
            atomicAdd(&g_cnt[mbase + idxs[j]], 1);
        }
    }
}

__global__ void scan_kernel() {
    if (threadIdx.x == 0) {
        int acc = 0;
        for (int i = 0; i < NSLOTS; i++) { g_off[i] = acc; acc += g_cnt[i]; }
    }
}

__global__ void scatter_kernel() {
    int p = blockIdx.x * blockDim.x + threadIdx.x;
    if (p >= NPAIRS) return;
    int slot = g_tope[p];
    int pos = atomicAdd(&g_cur[slot], 1);
    int g = g_off[slot] + pos;
    g_slot_tok[g] = p / TOPK;
    g_slot_w[g]   = g_topw[p];
    g_pair_row[p] = g;
}

// ---------------- fused gate/up GEMM + SiLU --------------------------------
// BM=128, BN=64, BK=16, 256 threads, per-thread 8x4 x two accumulators.
// mode 0: text experts, 1: vis experts, 2: shared expert.
__global__ void __launch_bounds__(256)
gateup_kernel(const float* __restrict__ X, const float* __restrict__ Wb,
              const float* __restrict__ Wu2, int mode)
{
    int I, ldw, M, baserow;
    const float *Wg, *Wu;
    float* outp; int ldo;
    if (mode == 0) {
        int s = blockIdx.z;
        I = TI; ldw = 2*TI;
        Wg = Wb + (size_t)s * HID * (2*TI); Wu = Wg + TI;
        M = g_cnt[s]; baserow = g_off[s];
        outp = g_hexp; ldo = TI;
    } else if (mode == 1) {
        int s = blockIdx.z;
        I = VI; ldw = 2*VI;
        Wg = Wb + (size_t)s * HID * (2*VI); Wu = Wg + VI;
        M = g_cnt[16+s]; baserow = g_off[16+s];
        outp = g_hexp; ldo = TI;
    } else {
        I = SI; ldw = SI;
        Wg = Wb; Wu = Wu2;
        M = T_TOKENS; baserow = 0;
        outp = g_hsh; ldo = SI;
    }
    int m0 = blockIdx.y * 128;
    int n0 = blockIdx.x * 64;
    if (m0 >= M || n0 >= I) return;

    __shared__ float As[16][132];
    __shared__ float Bg[16][68];
    __shared__ float Bu[16][68];

    int tid = threadIdx.x;
    int ar = tid >> 2;           // 0..63
    int ac = (tid & 3) << 2;     // 0,4,8,12
    int br = tid >> 4;           // 0..15
    int bc = (tid & 15) << 2;    // 0..60
    int ty = tid >> 4;           // 0..15
    int tx = tid & 15;           // 0..15

    int r0 = min(m0 + ar, M - 1);
    int r1 = min(m0 + 64 + ar, M - 1);
    int tok0 = (mode < 2) ? g_slot_tok[baserow + r0] : r0;
    int tok1 = (mode < 2) ? g_slot_tok[baserow + r1] : r1;
    const float* a0p = X + (size_t)tok0 * HID + ac;
    const float* a1p = X + (size_t)tok1 * HID + ac;
    const float* bgp = Wg + (size_t)br * ldw + n0 + bc;
    const float* bup = Wu + (size_t)br * ldw + n0 + bc;

    float accg[8][4], accu[8][4];
    #pragma unroll
    for (int i = 0; i < 8; i++)
        #pragma unroll
        for (int j = 0; j < 4; j++) { accg[i][j] = 0.f; accu[i][j] = 0.f; }

    for (int k0 = 0; k0 < HID; k0 += 16) {
        float4 a0 = *(const float4*)(a0p + k0);
        float4 a1 = *(const float4*)(a1p + k0);
        float4 bg = *(const float4*)(bgp + (size_t)k0 * ldw);
        float4 bu = *(const float4*)(bup + (size_t)k0 * ldw);
        As[ac+0][ar] = a0.x; As[ac+1][ar] = a0.y; As[ac+2][ar] = a0.z; As[ac+3][ar] = a0.w;
        As[ac+0][64+ar] = a1.x; As[ac+1][64+ar] = a1.y; As[ac+2][64+ar] = a1.z; As[ac+3][64+ar] = a1.w;
        *(float4*)&Bg[br][bc] = bg;
        *(float4*)&Bu[br][bc] = bu;
        __syncthreads();
        #pragma unroll
        for (int k = 0; k < 16; k++) {
            float a[8], bgv[4], buv[4];
            #pragma unroll
            for (int i = 0; i < 8; i++) a[i] = As[k][ty*8 + i];
            #pragma unroll
            for (int j = 0; j < 4; j++) { bgv[j] = Bg[k][tx*4 + j]; buv[j] = Bu[k][tx*4 + j]; }
            #pragma unroll
            for (int i = 0; i < 8; i++)
                #pragma unroll
                for (int j = 0; j < 4; j++) {
                    accg[i][j] += a[i] * bgv[j];
                    accu[i][j] += a[i] * buv[j];
                }
        }
        __syncthreads();
    }

    #pragma unroll
    for (int i = 0; i < 8; i++) {
        int m = m0 + ty*8 + i;
        if (m >= M) continue;
        #pragma unroll
        for (int j = 0; j < 4; j++) {
            int n = n0 + tx*4 + j;
            float g = accg[i][j];
            float h = (g / (1.f + expf(-g))) * accu[i][j];
            outp[(size_t)(baserow + m) * ldo + n] = h;
        }
    }
}

// ---------------- down-proj GEMM (+ per-row routing weight) ----------------
// BM=128, BN=128, BK=16, 256 threads, per-thread 8x8.
__global__ void __launch_bounds__(256)
down_kernel(const float* __restrict__ Wb, int mode)
{
    int I, M, baserow;
    const float* Wd;
    const float* A; int lda;
    float* outp; bool scl;
    if (mode == 0) {
        int s = blockIdx.z;
        I = TI; Wd = Wb + (size_t)s * TI * HID;
        M = g_cnt[s]; baserow = g_off[s];
        A = g_hexp; lda = TI; outp = g_oexp; scl = true;
    } else if (mode == 1) {
        int s = blockIdx.z;
        I = VI; Wd = Wb + (size_t)s * VI * HID;
        M = g_cnt[16+s]; baserow = g_off[16+s];
        A = g_hexp; lda = TI; outp = g_oexp; scl = true;
    } else {
        I = SI; Wd = Wb;
        M = T_TOKENS; baserow = 0;
        A = g_hsh; lda = SI; outp = g_osh; scl = false;
    }
    int m0 = blockIdx.y * 128, n0 = blockIdx.x * 128;
    if (m0 >= M) return;

    __shared__ float As[16][132];
    __shared__ float Bs[16][132];

    int tid = threadIdx.x;
    int ar = tid >> 2, ac = (tid & 3) << 2;
    int br = tid >> 5, bc = (tid & 31) << 2;
    int ty = tid >> 4, tx = tid & 15;

    int r0 = min(m0 + ar, M - 1), r1 = min(m0 + 64 + ar, M - 1);
    const float* a0p = A + (size_t)(baserow + r0) * lda + ac;
    const float* a1p = A + (size_t)(baserow + r1) * lda + ac;
    const float* b0p = Wd + (size_t)br * HID + n0 + bc;
    const float* b1p = Wd + (size_t)(br + 8) * HID + n0 + bc;

    float acc[8][8];
    #pragma unroll
    for (int i = 0; i < 8; i++)
        #pragma unroll
        for (int j = 0; j < 8; j++) acc[i][j] = 0.f;

    for (int k0 = 0; k0 < I; k0 += 16) {
        float4 a0 = *(const float4*)(a0p + k0);
        float4 a1 = *(const float4*)(a1p + k0);
        float4 b0 = *(const float4*)(b0p + (size_t)k0 * HID);
        float4 b1 = *(const float4*)(b1p + (size_t)k0 * HID);
        As[ac+0][ar] = a0.x; As[ac+1][ar] = a0.y; As[ac+2][ar] = a0.z; As[ac+3][ar] = a0.w;
        As[ac+0][64+ar] = a1.x; As[ac+1][64+ar] = a1.y; As[ac+2][64+ar] = a1.z; As[ac+3][64+ar] = a1.w;
        *(float4*)&Bs[br][bc]   = b0;
        *(float4*)&Bs[br+8][bc] = b1;
        __syncthreads();
        #pragma unroll
        for (int k = 0; k < 16; k++) {
            float a[8], b[8];
            #pragma unroll
            for (int i = 0; i < 8; i++) a[i] = As[k][ty*8 + i];
            #pragma unroll
            for (int j = 0; j < 8; j++) b[j] = Bs[k][tx*8 + j];
            #pragma unroll
            for (int i = 0; i < 8; i++)
                #pragma unroll
                for (int j = 0; j < 8; j++) acc[i][j] += a[i] * b[j];
        }
        __syncthreads();
    }

    #pragma unroll
    for (int i = 0; i < 8; i++) {
        int m = m0 + ty*8 + i;
        if (m >= M) continue;
        float w = scl ? g_slot_w[baserow + m] : 1.f;
        #pragma unroll
        for (int j = 0; j < 8; j++)
            outp[(size_t)(baserow + m) * HID + n0 + tx*8 + j] = acc[i][j] * w;
    }
}

// ---------------- finalize: gather 6 expert rows + shared ------------------
__global__ void __launch_bounds__(256)
finalize_kernel(float* __restrict__ out)
{
    int t = blockIdx.y;
    int h = blockIdx.x * 256 + threadIdx.x;
    float s = g_osh[(size_t)t * HID + h];
    #pragma unroll
    for (int j = 0; j < TOPK; j++) {
        int g = g_pair_row[t*TOPK + j];
        s += g_oexp[(size_t)g * HID + h];
    }
    out[(size_t)t * HID + h] = s;
}

// ---------------- launch ----------------------------------------------------
extern "C" void kernel_launch(void* const* d_in, const int* in_sizes, int n_in,
                              void* d_out, int out_size)
{
    (void)in_sizes; (void)n_in; (void)out_size;
    const float* x   = (const float*)d_in[0];
    const int*   tt  = (const int*)  d_in[1];
    const float* trw = (const float*)d_in[2];
    const float* trb = (const float*)d_in[3];
    const float* tgu = (const float*)d_in[4];
    const float* tdn = (const float*)d_in[5];
    const float* vrw = (const float*)d_in[6];
    const float* vrb = (const float*)d_in[7];
    const float* vgu = (const float*)d_in[8];
    const float* vdn = (const float*)d_in[9];
    const float* sg  = (const float*)d_in[10];
    const float* su  = (const float*)d_in[11];
    const float* sd  = (const float*)d_in[12];
    float* out        = (float*)d_out;
    float* out_logits = out + (size_t)T_TOKENS * HID;

    init_kernel<<<1, 32>>>();
    router_kernel<<<T_TOKENS, 128>>>(x, tt, trw, trb, vrw, vrb, out_logits);
    scan_kernel<<<1, 1>>>();
    scatter_kernel<<<NPAIRS/256, 256>>>();

    gateup_kernel<<<dim3(TI/64, 32, 16), 256>>>(x, tgu, nullptr, 0);
    gateup_kernel<<<dim3(VI/64, 32, 16), 256>>>(x, vgu, nullptr, 1);
    gateup_kernel<<<dim3(SI/64, T_TOKENS/128, 1), 256>>>(x, sg, su, 2);

    down_kernel<<<dim3(HID/128, 32, 16), 256>>>(tdn, 0);
    down_kernel<<<dim3(HID/128, 32, 16), 256>>>(vdn, 1);
    down_kernel<<<dim3(HID/128, T_TOKENS/128, 1), 256>>>(sd, 2);

    finalize_kernel<<<dim3(HID/256, T_TOKENS), 256>>>(out);
}